// round 9
// baseline (speedup 1.0000x reference)
#include <cuda_runtime.h>
#include <cuda_bf16.h>
#include <cstdint>

#define N_ 50000
#define F_ 128
#define E_ 800000
#define K_ 64
#define L_ 3

using u64 = unsigned long long;

// ---------------------------------------------------------------------------
// Scratch (static device globals — no runtime allocation)
// ---------------------------------------------------------------------------
__device__ float g_m[(size_t)N_ * F_];      // xi, then m (edge kernel adds into it)
__device__ float g_xjall[(size_t)N_ * F_];  // ssp(xa@Wj+bj)
__device__ float g_y[(size_t)N_ * F_];      // residual temp
// bf16-split transposed node weights: [mat 0..8][c 0..127][k 0..127]
__device__ __nv_bfloat16 g_wthi[9 * 128 * 128];
__device__ __nv_bfloat16 g_wtlo[9 * 128 * 128];
// bf16-split transposed Wk2f: [c 0..127][k 0..63]
__device__ __nv_bfloat16 g_wkhi[128 * 64];
__device__ __nv_bfloat16 g_wklo[128 * 64];

__device__ __forceinline__ float ssp(float v) {
    // softplus(v) - ln2 via fast MUFU path; abs err ~1e-7
    float ax = fabsf(v);
    return fmaxf(v, 0.0f) + __logf(1.0f + __expf(-ax)) -
           0.69314718055994530942f;
}
__device__ __forceinline__ float4 ssp4(float4 v) {
    v.x = ssp(v.x); v.y = ssp(v.y); v.z = ssp(v.z); v.w = ssp(v.w);
    return v;
}

__device__ __forceinline__ uint32_t smem_u32(const void* p) {
    uint32_t a;
    asm("{ .reg .u64 t; cvta.to.shared.u64 t, %1; cvt.u32.u64 %0, t; }"
        : "=r"(a) : "l"(p));
    return a;
}

// ldmatrix x4 (non-transposed), b16
__device__ __forceinline__ void ldsm4(unsigned* r, uint32_t addr) {
    asm volatile(
        "ldmatrix.sync.aligned.m8n8.x4.shared.b16 {%0,%1,%2,%3}, [%4];"
        : "=r"(r[0]), "=r"(r[1]), "=r"(r[2]), "=r"(r[3]) : "r"(addr));
}

// mma m16n8k16 bf16 -> f32, accumulate in place
__device__ __forceinline__ void mma16816(float* d, const unsigned* a,
                                         const unsigned b0, const unsigned b1) {
    asm volatile(
        "mma.sync.aligned.m16n8k16.row.col.f32.bf16.bf16.f32 "
        "{%0,%1,%2,%3}, {%4,%5,%6,%7}, {%8,%9}, {%0,%1,%2,%3};"
        : "+f"(d[0]), "+f"(d[1]), "+f"(d[2]), "+f"(d[3])
        : "r"(a[0]), "r"(a[1]), "r"(a[2]), "r"(a[3]), "r"(b0), "r"(b1));
}

// ---------------------------------------------------------------------------
// Pack node weights: W[k][c] fp32 -> WT_hi/lo[c][k] bf16 (one launch, 9 mats)
// ---------------------------------------------------------------------------
__global__ void packw_kernel(const float* __restrict__ Wi,
                             const float* __restrict__ Wj,
                             const float* __restrict__ Wr1,
                             const float* __restrict__ Wr2,
                             const float* __restrict__ Wf,
                             __nv_bfloat16* __restrict__ hi,
                             __nv_bfloat16* __restrict__ lo) {
    int m = blockIdx.y;
    const float* W;
    if (m == 0) W = Wi;
    else if (m == 1) W = Wj;
    else if (m < 5) W = Wr1 + (size_t)(m - 2) * F_ * F_;
    else if (m < 8) W = Wr2 + (size_t)(m - 5) * F_ * F_;
    else W = Wf;
    int i = blockIdx.x * blockDim.x + threadIdx.x;
    if (i < 128 * 128) {
        int c = i >> 7, k = i & 127;
        float f = W[k * 128 + c];
        __nv_bfloat16 h = __float2bfloat16_rn(f);
        __nv_bfloat16 l = __float2bfloat16_rn(f - __bfloat162float(h));
        hi[(size_t)m * 16384 + i] = h;
        lo[(size_t)m * 16384 + i] = l;
    }
}

// Pack Wk2f: [k 0..63][c 0..127] fp32 -> [c][k] hi/lo bf16
__global__ void packwk_kernel(const float* __restrict__ W,
                              __nv_bfloat16* __restrict__ hi,
                              __nv_bfloat16* __restrict__ lo) {
    int i = blockIdx.x * blockDim.x + threadIdx.x;
    if (i < 128 * 64) {
        int c = i >> 6, k = i & 63;
        float f = W[k * 128 + c];
        __nv_bfloat16 h = __float2bfloat16_rn(f);
        __nv_bfloat16 l = __float2bfloat16_rn(f - __bfloat162float(h));
        hi[i] = h;
        lo[i] = l;
    }
}

// ---------------------------------------------------------------------------
// mma.sync node GEMM: C = ep( [ssp?](A) @ W + bias ), 64x128x128 tiles.
// 2-term bf16 split: D = Ahi*Whi + Ahi*Wlo + Alo*Whi (fp32 accum).
// Term-OUTER accumulation order: consecutive HMMAs into the same
// accumulator are separated by 7 independent ones (breaks RAW chains).
// EP: 0 -> r, 1 -> C+r, 2 -> u*x + r
// ---------------------------------------------------------------------------
#define LDA 136
#define APLANE (64 * LDA * 2)      // 17408 B
#define WPLANE (128 * LDA * 2)     // 34816 B
#define SM_AHI 0
#define SM_ALO (SM_AHI + APLANE)
#define SM_WHI (SM_ALO + APLANE)
#define SM_WLO (SM_WHI + WPLANE)
#define SM_TOTAL (SM_WLO + WPLANE) // 104448 B -> 2 CTAs/SM

template <bool IN_ACT, bool OUT_ACT, int EP>
__global__ __launch_bounds__(256, 2)
void gemm_mma(const float* __restrict__ A,
              const __nv_bfloat16* __restrict__ wthi,
              const __nv_bfloat16* __restrict__ wtlo,
              const float* __restrict__ bias, float* __restrict__ C,
              const float* __restrict__ x, const float* __restrict__ u,
              int n) {
    extern __shared__ __align__(16) char sm[];
    uint32_t smb = smem_u32(sm);
    int tid = threadIdx.x;
    int wid = tid >> 5;
    int lane = tid & 31;
    int row0 = blockIdx.x * 64;

    // stage W hi/lo: [c][k] row-major -> [128][LDA] padded (2048 uint4/plane)
    {
        const uint4* srcH = reinterpret_cast<const uint4*>(wthi);
        const uint4* srcL = reinterpret_cast<const uint4*>(wtlo);
#pragma unroll
        for (int it = 0; it < 8; ++it) {
            int idx = tid + it * 256;      // 0..2047
            int row = idx >> 4;
            int seg = idx & 15;
            uint32_t off = (uint32_t)(row * LDA + seg * 8) * 2;
            *reinterpret_cast<uint4*>(sm + SM_WHI + off) = srcH[idx];
            *reinterpret_cast<uint4*>(sm + SM_WLO + off) = srcL[idx];
        }
    }
    // stage A hi/lo: fp32 -> ssp? -> bf16 split (64 rows, 2048 float4)
    {
        const float4* A4 = reinterpret_cast<const float4*>(A);
#pragma unroll
        for (int it = 0; it < 8; ++it) {
            int idx = tid + it * 256;      // 0..2047
            int row = idx >> 5;            // 0..63
            int k4 = idx & 31;
            float4 v = make_float4(0.f, 0.f, 0.f, 0.f);
            if (row0 + row < n) v = A4[(size_t)(row0 + row) * 32 + k4];
            if (IN_ACT) v = ssp4(v);
            __nv_bfloat162 h01 = __floats2bfloat162_rn(v.x, v.y);
            __nv_bfloat162 h23 = __floats2bfloat162_rn(v.z, v.w);
            __nv_bfloat162 l01 = __floats2bfloat162_rn(
                v.x - __bfloat162float(h01.x), v.y - __bfloat162float(h01.y));
            __nv_bfloat162 l23 = __floats2bfloat162_rn(
                v.z - __bfloat162float(h23.x), v.w - __bfloat162float(h23.y));
            uint32_t off = (uint32_t)(row * LDA + k4 * 4) * 2;
            u64 hv = ((u64)*reinterpret_cast<uint32_t*>(&h23) << 32) |
                     *reinterpret_cast<uint32_t*>(&h01);
            u64 lv = ((u64)*reinterpret_cast<uint32_t*>(&l23) << 32) |
                     *reinterpret_cast<uint32_t*>(&l01);
            *reinterpret_cast<u64*>(sm + SM_AHI + off) = hv;
            *reinterpret_cast<u64*>(sm + SM_ALO + off) = lv;
        }
    }
    __syncthreads();

    int warp_m = wid & 1;        // 2 row groups x 32 rows
    int warp_n = wid >> 1;       // 4 col groups x 32 cols

    float d[2][4][4];
#pragma unroll
    for (int mt = 0; mt < 2; ++mt)
#pragma unroll
        for (int nt = 0; nt < 4; ++nt)
#pragma unroll
            for (int q = 0; q < 4; ++q) d[mt][nt][q] = 0.f;

    int a_row = warp_m * 32 + (lane & 15);
    int a_k8 = (lane >> 4) * 8;
    int b_n = warp_n * 32 + (lane >> 4) * 8 + (lane & 7);
    int b_k8 = ((lane >> 3) & 1) * 8;

#pragma unroll
    for (int ks = 0; ks < 8; ++ks) {
        int kb = ks * 16;
        unsigned bh[2][4], bl[2][4], ah[2][4], al[2][4];
#pragma unroll
        for (int p = 0; p < 2; ++p) {
            uint32_t boff = (uint32_t)((b_n + p * 16) * LDA + kb + b_k8) * 2;
            ldsm4(bh[p], smb + SM_WHI + boff);
            ldsm4(bl[p], smb + SM_WLO + boff);
        }
#pragma unroll
        for (int mt = 0; mt < 2; ++mt) {
            uint32_t aoff = (uint32_t)((a_row + mt * 16) * LDA + kb + a_k8) * 2;
            ldsm4(ah[mt], smb + SM_AHI + aoff);
            ldsm4(al[mt], smb + SM_ALO + aoff);
        }
        // term-outer: 8 independent accumulators between same-d HMMAs
#pragma unroll
        for (int term = 0; term < 3; ++term) {
#pragma unroll
            for (int mt = 0; mt < 2; ++mt) {
#pragma unroll
                for (int nt = 0; nt < 4; ++nt) {
                    const unsigned* af = (term == 2) ? al[mt] : ah[mt];
                    const unsigned* bf =
                        (term == 1) ? bl[nt >> 1] : bh[nt >> 1];
                    unsigned b0 = bf[(nt & 1) * 2];
                    unsigned b1 = bf[(nt & 1) * 2 + 1];
                    mma16816(d[mt][nt], af, b0, b1);
                }
            }
        }
    }

    // epilogue
    const float2* bias2 = reinterpret_cast<const float2*>(bias);
    float2* C2 = reinterpret_cast<float2*>(C);
    const float2* x2 = reinterpret_cast<const float2*>(x);
    const float2* u2 = reinterpret_cast<const float2*>(u);

#pragma unroll
    for (int mt = 0; mt < 2; ++mt) {
#pragma unroll
        for (int half = 0; half < 2; ++half) {
            int r = row0 + warp_m * 32 + mt * 16 + (lane >> 2) + half * 8;
            if (r >= n) continue;
#pragma unroll
            for (int nt = 0; nt < 4; ++nt) {
                int c = warp_n * 32 + nt * 8 + (lane & 3) * 2;
                int ci = c >> 1;
                float2 bb = bias2[ci];
                float2 v;
                v.x = d[mt][nt][half * 2 + 0] + bb.x;
                v.y = d[mt][nt][half * 2 + 1] + bb.y;
                size_t gi = (size_t)r * 64 + ci;
                if constexpr (EP == 1) {
                    float2 o = C2[gi];
                    v.x += o.x; v.y += o.y;
                }
                if constexpr (EP == 2) {
                    float2 xv = x2[gi];
                    float2 uv = u2[ci];
                    v.x += uv.x * xv.x; v.y += uv.y * xv.y;
                }
                if constexpr (OUT_ACT) { v.x = ssp(v.x); v.y = ssp(v.y); }
                C2[gi] = v;
            }
        }
    }
}

// ---------------------------------------------------------------------------
// Edge kernel, MMA version (term-outer accumulation). Per 512-edge block,
// 8 tiles of 64 edges: stage rbf -> bf16 hi/lo; MMA g = rbf @ Wk2f^T;
// dump g to smem; sequential gather/gate/run-length-scatter.
// ---------------------------------------------------------------------------
#define ELDK 72
#define EW_PLANE (128 * ELDK * 2)   // 18432
#define EA_PLANE (64 * ELDK * 2)    // 9216
#define EG_LD 132
#define ESM_WHI 0
#define ESM_WLO (ESM_WHI + EW_PLANE)
#define ESM_AHI (ESM_WLO + EW_PLANE)
#define ESM_ALO (ESM_AHI + EA_PLANE)
#define ESM_G   (ESM_ALO + EA_PLANE)
#define ESM_TOTAL (ESM_G + 64 * EG_LD * 4)   // 89088 B

__global__ __launch_bounds__(256, 2)
void edge_mma(const float* __restrict__ rbf,
              const __nv_bfloat16* __restrict__ wkhi,
              const __nv_bfloat16* __restrict__ wklo,
              const float* __restrict__ xjall, const int* __restrict__ ii,
              const int* __restrict__ jj, float* __restrict__ mout) {
    extern __shared__ __align__(16) char sm[];
    uint32_t smb = smem_u32(sm);
    int tid = threadIdx.x;
    int wid = tid >> 5;
    int lane = tid & 31;

    // stage W planes: [128 c][64 k] bf16, 1024 uint4 each
    {
        const uint4* srcH = reinterpret_cast<const uint4*>(wkhi);
        const uint4* srcL = reinterpret_cast<const uint4*>(wklo);
#pragma unroll
        for (int it = 0; it < 4; ++it) {
            int idx = tid + it * 256;      // 0..1023
            int row = idx >> 3;
            int seg = idx & 7;
            uint32_t off = (uint32_t)(row * ELDK + seg * 8) * 2;
            *reinterpret_cast<uint4*>(sm + ESM_WHI + off) = srcH[idx];
            *reinterpret_cast<uint4*>(sm + ESM_WLO + off) = srcL[idx];
        }
    }

    int warp_m = wid & 1;
    int warp_n = wid >> 1;
    int a_row = warp_m * 32 + (lane & 15);
    int a_k8 = (lane >> 4) * 8;
    int b_n = warp_n * 32 + (lane >> 4) * 8 + (lane & 7);
    int b_k8 = ((lane >> 3) & 1) * 8;

    int tx = tid & 31;      // col group: cols tx*4..tx*4+3
    int eg = tid >> 5;      // edge group of 8 within tile
    int c0 = tx * 4;
    long base = (long)blockIdx.x * 512;

    const float4* rbf4 = reinterpret_cast<const float4*>(rbf);

    int cur_i = -1;
    float racc[4] = {0.f, 0.f, 0.f, 0.f};

    for (int t = 0; t < 8; ++t) {
        __syncthreads();   // protect A and G reuse from previous tile
        // stage rbf tile: 64 edges x 64 k (1024 float4), split to bf16 hi/lo
#pragma unroll
        for (int s = 0; s < 4; ++s) {
            int idx = tid + s * 256;       // 0..1023
            int er = idx >> 4;             // 0..63
            int k4 = idx & 15;
            long e = base + t * 64 + er;
            float4 v = make_float4(0.f, 0.f, 0.f, 0.f);
            if (e < E_) v = rbf4[e * 16 + k4];
            __nv_bfloat162 h01 = __floats2bfloat162_rn(v.x, v.y);
            __nv_bfloat162 h23 = __floats2bfloat162_rn(v.z, v.w);
            __nv_bfloat162 l01 = __floats2bfloat162_rn(
                v.x - __bfloat162float(h01.x), v.y - __bfloat162float(h01.y));
            __nv_bfloat162 l23 = __floats2bfloat162_rn(
                v.z - __bfloat162float(h23.x), v.w - __bfloat162float(h23.y));
            uint32_t off = (uint32_t)(er * ELDK + k4 * 4) * 2;
            u64 hv = ((u64)*reinterpret_cast<uint32_t*>(&h23) << 32) |
                     *reinterpret_cast<uint32_t*>(&h01);
            u64 lv = ((u64)*reinterpret_cast<uint32_t*>(&l23) << 32) |
                     *reinterpret_cast<uint32_t*>(&l01);
            *reinterpret_cast<u64*>(sm + ESM_AHI + off) = hv;
            *reinterpret_cast<u64*>(sm + ESM_ALO + off) = lv;
        }
        __syncthreads();

        // MMA: g[64 e][128 c] = rbf @ Wk2f^T, 3-term split, K=64
        float d[2][4][4];
#pragma unroll
        for (int mt = 0; mt < 2; ++mt)
#pragma unroll
            for (int nt = 0; nt < 4; ++nt)
#pragma unroll
                for (int q = 0; q < 4; ++q) d[mt][nt][q] = 0.f;

#pragma unroll
        for (int ks = 0; ks < 4; ++ks) {
            int kb = ks * 16;
            unsigned bh[2][4], bl[2][4], ah[2][4], al[2][4];
#pragma unroll
            for (int p = 0; p < 2; ++p) {
                uint32_t boff =
                    (uint32_t)((b_n + p * 16) * ELDK + kb + b_k8) * 2;
                ldsm4(bh[p], smb + ESM_WHI + boff);
                ldsm4(bl[p], smb + ESM_WLO + boff);
            }
#pragma unroll
            for (int mt = 0; mt < 2; ++mt) {
                uint32_t aoff =
                    (uint32_t)((a_row + mt * 16) * ELDK + kb + a_k8) * 2;
                ldsm4(ah[mt], smb + ESM_AHI + aoff);
                ldsm4(al[mt], smb + ESM_ALO + aoff);
            }
            // term-outer accumulation
#pragma unroll
            for (int term = 0; term < 3; ++term) {
#pragma unroll
                for (int mt = 0; mt < 2; ++mt) {
#pragma unroll
                    for (int nt = 0; nt < 4; ++nt) {
                        const unsigned* af = (term == 2) ? al[mt] : ah[mt];
                        const unsigned* bf =
                            (term == 1) ? bl[nt >> 1] : bh[nt >> 1];
                        unsigned b0 = bf[(nt & 1) * 2];
                        unsigned b1 = bf[(nt & 1) * 2 + 1];
                        mma16816(d[mt][nt], af, b0, b1);
                    }
                }
            }
        }

        // dump g to smem (fp32, padded rows)
#pragma unroll
        for (int mt = 0; mt < 2; ++mt)
#pragma unroll
            for (int half = 0; half < 2; ++half) {
                int row = warp_m * 32 + mt * 16 + (lane >> 2) + half * 8;
#pragma unroll
                for (int nt = 0; nt < 4; ++nt) {
                    int col = warp_n * 32 + nt * 8 + (lane & 3) * 2;
                    float2 v;
                    v.x = d[mt][nt][half * 2 + 0];
                    v.y = d[mt][nt][half * 2 + 1];
                    *reinterpret_cast<float2*>(
                        sm + ESM_G + (uint32_t)(row * EG_LD + col) * 4) = v;
                }
            }
        __syncthreads();

        // epilogue: gather + gate + run-length scatter (idx_i sorted)
#pragma unroll
        for (int s = 0; s < 8; ++s) {
            long e = base + t * 64 + eg * 8 + s;
            if (e >= E_) continue;
            float4 g4 = *reinterpret_cast<const float4*>(
                sm + ESM_G + (uint32_t)((eg * 8 + s) * EG_LD + c0) * 4);
            int i = __ldg(ii + e);
            int j = __ldg(jj + e);
            float4 xv = __ldg(reinterpret_cast<const float4*>(
                                  xjall + (size_t)j * 128) + tx);
            float v0 = g4.x * xv.x;
            float v1 = g4.y * xv.y;
            float v2 = g4.z * xv.z;
            float v3 = g4.w * xv.w;
            if (i != cur_i) {
                if (cur_i >= 0) {
                    float* dst = mout + (size_t)cur_i * 128 + c0;
                    atomicAdd(dst + 0, racc[0]);
                    atomicAdd(dst + 1, racc[1]);
                    atomicAdd(dst + 2, racc[2]);
                    atomicAdd(dst + 3, racc[3]);
                }
                cur_i = i;
                racc[0] = v0; racc[1] = v1; racc[2] = v2; racc[3] = v3;
            } else {
                racc[0] += v0; racc[1] += v1; racc[2] += v2; racc[3] += v3;
            }
        }
    }
    if (cur_i >= 0) {
        float* dst = mout + (size_t)cur_i * 128 + c0;
        atomicAdd(dst + 0, racc[0]);
        atomicAdd(dst + 1, racc[1]);
        atomicAdd(dst + 2, racc[2]);
        atomicAdd(dst + 3, racc[3]);
    }
}

// ---------------------------------------------------------------------------
// Launch
// ---------------------------------------------------------------------------
extern "C" void kernel_launch(void* const* d_in, const int* in_sizes, int n_in,
                              void* d_out, int out_size) {
    const float* x    = (const float*)d_in[0];
    const float* rbf  = (const float*)d_in[1];
    const float* Wk2f = (const float*)d_in[2];
    const float* Wi   = (const float*)d_in[3];
    const float* bi   = (const float*)d_in[4];
    const float* Wj   = (const float*)d_in[5];
    const float* bj   = (const float*)d_in[6];
    const float* Wr1  = (const float*)d_in[7];
    const float* br1  = (const float*)d_in[8];
    const float* Wr2  = (const float*)d_in[9];
    const float* br2  = (const float*)d_in[10];
    const float* Wf   = (const float*)d_in[11];
    const float* bfb  = (const float*)d_in[12];
    const float* u    = (const float*)d_in[13];
    const int* idx_i  = (const int*)d_in[14];
    const int* idx_j  = (const int*)d_in[15];
    float* out = (float*)d_out;

    void *p_m, *p_xjall, *p_y, *p_hi, *p_lo, *p_wkh, *p_wkl;
    cudaGetSymbolAddress(&p_m, g_m);
    cudaGetSymbolAddress(&p_xjall, g_xjall);
    cudaGetSymbolAddress(&p_y, g_y);
    cudaGetSymbolAddress(&p_hi, g_wthi);
    cudaGetSymbolAddress(&p_lo, g_wtlo);
    cudaGetSymbolAddress(&p_wkh, g_wkhi);
    cudaGetSymbolAddress(&p_wkl, g_wklo);
    float* m = (float*)p_m;
    float* xjall = (float*)p_xjall;
    float* y = (float*)p_y;
    __nv_bfloat16* whi = (__nv_bfloat16*)p_hi;
    __nv_bfloat16* wlo = (__nv_bfloat16*)p_lo;
    __nv_bfloat16* wkhi = (__nv_bfloat16*)p_wkh;
    __nv_bfloat16* wklo = (__nv_bfloat16*)p_wkl;

    cudaFuncSetAttribute(gemm_mma<true, true, 0>,
                         cudaFuncAttributeMaxDynamicSharedMemorySize, SM_TOTAL);
    cudaFuncSetAttribute(gemm_mma<false, false, 1>,
                         cudaFuncAttributeMaxDynamicSharedMemorySize, SM_TOTAL);
    cudaFuncSetAttribute(gemm_mma<true, false, 2>,
                         cudaFuncAttributeMaxDynamicSharedMemorySize, SM_TOTAL);
    cudaFuncSetAttribute(edge_mma,
                         cudaFuncAttributeMaxDynamicSharedMemorySize, ESM_TOTAL);

    // one-time weight packing
    dim3 pw(64, 9);
    packw_kernel<<<pw, 256>>>(Wi, Wj, Wr1, Wr2, Wf, whi, wlo);
    packwk_kernel<<<32, 256>>>(Wk2f, wkhi, wklo);

    int gemm_blocks = (N_ + 63) / 64;       // 782
    int edge_blocks = (E_ + 511) / 512;     // 1563

    // m = xi = ssp(ssp(x) @ Wi + bi)
    gemm_mma<true, true, 0><<<gemm_blocks, 256, SM_TOTAL>>>(
        x, whi + 0 * 16384, wlo + 0 * 16384, bi, m, nullptr, nullptr, N_);
    // xjall = ssp(ssp(x) @ Wj + bj)
    gemm_mma<true, true, 0><<<gemm_blocks, 256, SM_TOTAL>>>(
        x, whi + 1 * 16384, wlo + 1 * 16384, bj, xjall, nullptr, nullptr, N_);
    // m += segment_sum((rbf@Wk2f) * xjall[idx_j], idx_i)
    edge_mma<<<edge_blocks, 256, ESM_TOTAL>>>(rbf, wkhi, wklo, xjall,
                                              idx_i, idx_j, m);

    // residual blocks
    for (int l = 0; l < L_; ++l) {
        gemm_mma<true, true, 0><<<gemm_blocks, 256, SM_TOTAL>>>(
            m, whi + (2 + l) * 16384, wlo + (2 + l) * 16384,
            br1 + (size_t)l * F_, y, nullptr, nullptr, N_);
        gemm_mma<false, false, 1><<<gemm_blocks, 256, SM_TOTAL>>>(
            y, whi + (5 + l) * 16384, wlo + (5 + l) * 16384,
            br2 + (size_t)l * F_, m, nullptr, nullptr, N_);
    }

    // out = u * x + ssp(m) @ Wf + bf
    gemm_mma<true, false, 2><<<gemm_blocks, 256, SM_TOTAL>>>(
        m, whi + 8 * 16384, wlo + 8 * 16384, bfb, out, x, u, N_);
}

// round 10
// speedup vs baseline: 1.2623x; 1.2623x over previous
#include <cuda_runtime.h>
#include <cuda_bf16.h>
#include <cstdint>

#define N_ 50000
#define F_ 128
#define E_ 800000
#define K_ 64
#define L_ 3

using u64 = unsigned long long;

// ---------------------------------------------------------------------------
// Scratch (static device globals — no runtime allocation)
// ---------------------------------------------------------------------------
__device__ float g_m[(size_t)N_ * F_];      // xi, then m (edge kernel adds into it)
__device__ float g_xjall[(size_t)N_ * F_];  // ssp(xa@Wj+bj)
__device__ float g_y[(size_t)N_ * F_];      // residual temp
// bf16-split transposed node weights: [mat 0..8][c 0..127][k 0..127]
__device__ __nv_bfloat16 g_wthi[9 * 128 * 128];
__device__ __nv_bfloat16 g_wtlo[9 * 128 * 128];
// bf16-split transposed Wk2f: [c 0..127][k 0..63]
__device__ __nv_bfloat16 g_wkhi[128 * 64];
__device__ __nv_bfloat16 g_wklo[128 * 64];

__device__ __forceinline__ float ssp(float v) {
    float ax = fabsf(v);
    return fmaxf(v, 0.0f) + __logf(1.0f + __expf(-ax)) -
           0.69314718055994530942f;
}
__device__ __forceinline__ float4 ssp4(float4 v) {
    v.x = ssp(v.x); v.y = ssp(v.y); v.z = ssp(v.z); v.w = ssp(v.w);
    return v;
}

__device__ __forceinline__ uint32_t smem_u32(const void* p) {
    uint32_t a;
    asm("{ .reg .u64 t; cvta.to.shared.u64 t, %1; cvt.u32.u64 %0, t; }"
        : "=r"(a) : "l"(p));
    return a;
}

__device__ __forceinline__ void ldsm4(unsigned* r, uint32_t addr) {
    asm volatile(
        "ldmatrix.sync.aligned.m8n8.x4.shared.b16 {%0,%1,%2,%3}, [%4];"
        : "=r"(r[0]), "=r"(r[1]), "=r"(r[2]), "=r"(r[3]) : "r"(addr));
}

__device__ __forceinline__ void mma16816(float* d, const unsigned* a,
                                         const unsigned b0, const unsigned b1) {
    asm volatile(
        "mma.sync.aligned.m16n8k16.row.col.f32.bf16.bf16.f32 "
        "{%0,%1,%2,%3}, {%4,%5,%6,%7}, {%8,%9}, {%0,%1,%2,%3};"
        : "+f"(d[0]), "+f"(d[1]), "+f"(d[2]), "+f"(d[3])
        : "r"(a[0]), "r"(a[1]), "r"(a[2]), "r"(a[3]), "r"(b0), "r"(b1));
}

// hi/lo bf16 split of a float4 into two packed u64s
__device__ __forceinline__ void split4(float4 v, u64& hv, u64& lv) {
    __nv_bfloat162 h01 = __floats2bfloat162_rn(v.x, v.y);
    __nv_bfloat162 h23 = __floats2bfloat162_rn(v.z, v.w);
    __nv_bfloat162 l01 = __floats2bfloat162_rn(
        v.x - __bfloat162float(h01.x), v.y - __bfloat162float(h01.y));
    __nv_bfloat162 l23 = __floats2bfloat162_rn(
        v.z - __bfloat162float(h23.x), v.w - __bfloat162float(h23.y));
    hv = ((u64)*reinterpret_cast<uint32_t*>(&h23) << 32) |
         *reinterpret_cast<uint32_t*>(&h01);
    lv = ((u64)*reinterpret_cast<uint32_t*>(&l23) << 32) |
         *reinterpret_cast<uint32_t*>(&l01);
}

// ---------------------------------------------------------------------------
// Pack node weights: W[k][c] fp32 -> WT_hi/lo[c][k] bf16 (one launch, 9 mats)
// ---------------------------------------------------------------------------
__global__ void packw_kernel(const float* __restrict__ Wi,
                             const float* __restrict__ Wj,
                             const float* __restrict__ Wr1,
                             const float* __restrict__ Wr2,
                             const float* __restrict__ Wf,
                             __nv_bfloat16* __restrict__ hi,
                             __nv_bfloat16* __restrict__ lo) {
    int m = blockIdx.y;
    const float* W;
    if (m == 0) W = Wi;
    else if (m == 1) W = Wj;
    else if (m < 5) W = Wr1 + (size_t)(m - 2) * F_ * F_;
    else if (m < 8) W = Wr2 + (size_t)(m - 5) * F_ * F_;
    else W = Wf;
    int i = blockIdx.x * blockDim.x + threadIdx.x;
    if (i < 128 * 128) {
        int c = i >> 7, k = i & 127;
        float f = W[k * 128 + c];
        __nv_bfloat16 h = __float2bfloat16_rn(f);
        __nv_bfloat16 l = __float2bfloat16_rn(f - __bfloat162float(h));
        hi[(size_t)m * 16384 + i] = h;
        lo[(size_t)m * 16384 + i] = l;
    }
}

__global__ void packwk_kernel(const float* __restrict__ W,
                              __nv_bfloat16* __restrict__ hi,
                              __nv_bfloat16* __restrict__ lo) {
    int i = blockIdx.x * blockDim.x + threadIdx.x;
    if (i < 128 * 64) {
        int c = i >> 6, k = i & 63;
        float f = W[k * 128 + c];
        __nv_bfloat16 h = __float2bfloat16_rn(f);
        __nv_bfloat16 l = __float2bfloat16_rn(f - __bfloat162float(h));
        hi[i] = h;
        lo[i] = l;
    }
}

// ---------------------------------------------------------------------------
// mma.sync node GEMM: 64x64x128 tiles (N split across 2 CTAs per row tile).
// 68KB smem -> 3 CTAs/SM for phase overlap.
// 8 warps in 2x4: warp = 32 rows x 16 cols (2 m16 x 2 n8 tiles).
// EP: 0 -> r, 1 -> C+r, 2 -> u*x + r
// ---------------------------------------------------------------------------
#define LDA 136
#define TPL (64 * LDA * 2)         // 17408 B
#define SM_AHI 0
#define SM_ALO (SM_AHI + TPL)
#define SM_WHI (SM_ALO + TPL)
#define SM_WLO (SM_WHI + TPL)
#define SM_TOTAL (SM_WLO + TPL)    // 69632 B -> 3 CTAs/SM

template <bool IN_ACT, bool OUT_ACT, int EP>
__global__ __launch_bounds__(256, 3)
void gemm_mma(const float* __restrict__ A,
              const __nv_bfloat16* __restrict__ wthi,
              const __nv_bfloat16* __restrict__ wtlo,
              const float* __restrict__ bias, float* __restrict__ C,
              const float* __restrict__ x, const float* __restrict__ u,
              int n) {
    extern __shared__ __align__(16) char sm[];
    uint32_t smb = smem_u32(sm);
    int tid = threadIdx.x;
    int wid = tid >> 5;
    int lane = tid & 31;
    int row0 = (blockIdx.x >> 1) * 64;
    int ch = (blockIdx.x & 1);         // column half: cols [ch*64, ch*64+64)

    // stage W hi/lo: rows c in [ch*64, ch*64+64), [64][LDA] padded
    {
        const uint4* srcH =
            reinterpret_cast<const uint4*>(wthi + ch * 64 * 128);
        const uint4* srcL =
            reinterpret_cast<const uint4*>(wtlo + ch * 64 * 128);
#pragma unroll
        for (int it = 0; it < 4; ++it) {
            int idx = tid + it * 256;      // 0..1023
            int row = idx >> 4;
            int seg = idx & 15;
            uint32_t off = (uint32_t)(row * LDA + seg * 8) * 2;
            *reinterpret_cast<uint4*>(sm + SM_WHI + off) = srcH[idx];
            *reinterpret_cast<uint4*>(sm + SM_WLO + off) = srcL[idx];
        }
    }
    // stage A hi/lo: 64 rows x 128 k (2048 float4)
    {
        const float4* A4 = reinterpret_cast<const float4*>(A);
#pragma unroll
        for (int it = 0; it < 8; ++it) {
            int idx = tid + it * 256;      // 0..2047
            int row = idx >> 5;            // 0..63
            int k4 = idx & 31;
            float4 v = make_float4(0.f, 0.f, 0.f, 0.f);
            if (row0 + row < n) v = A4[(size_t)(row0 + row) * 32 + k4];
            if (IN_ACT) v = ssp4(v);
            u64 hv, lv;
            split4(v, hv, lv);
            uint32_t off = (uint32_t)(row * LDA + k4 * 4) * 2;
            *reinterpret_cast<u64*>(sm + SM_AHI + off) = hv;
            *reinterpret_cast<u64*>(sm + SM_ALO + off) = lv;
        }
    }
    __syncthreads();

    int warp_m = wid & 1;        // 2 row groups x 32 rows
    int warp_n = wid >> 1;       // 4 col groups x 16 cols

    float d[2][2][4];
#pragma unroll
    for (int mt = 0; mt < 2; ++mt)
#pragma unroll
        for (int nt = 0; nt < 2; ++nt)
#pragma unroll
            for (int q = 0; q < 4; ++q) d[mt][nt][q] = 0.f;

    int a_row = warp_m * 32 + (lane & 15);
    int a_k8 = (lane >> 4) * 8;
    int b_n = warp_n * 16 + (lane >> 4) * 8 + (lane & 7);
    int b_k8 = ((lane >> 3) & 1) * 8;

#pragma unroll
    for (int ks = 0; ks < 8; ++ks) {
        int kb = ks * 16;
        unsigned bh[4], bl[4], ah[2][4], al[2][4];
        {
            uint32_t boff = (uint32_t)(b_n * LDA + kb + b_k8) * 2;
            ldsm4(bh, smb + SM_WHI + boff);
            ldsm4(bl, smb + SM_WLO + boff);
        }
#pragma unroll
        for (int mt = 0; mt < 2; ++mt) {
            uint32_t aoff = (uint32_t)((a_row + mt * 16) * LDA + kb + a_k8) * 2;
            ldsm4(ah[mt], smb + SM_AHI + aoff);
            ldsm4(al[mt], smb + SM_ALO + aoff);
        }
#pragma unroll
        for (int term = 0; term < 3; ++term) {
#pragma unroll
            for (int mt = 0; mt < 2; ++mt) {
#pragma unroll
                for (int nt = 0; nt < 2; ++nt) {
                    const unsigned* af = (term == 2) ? al[mt] : ah[mt];
                    const unsigned* bf = (term == 1) ? bl : bh;
                    mma16816(d[mt][nt], af, bf[nt * 2], bf[nt * 2 + 1]);
                }
            }
        }
    }

    // epilogue
    const float2* bias2 = reinterpret_cast<const float2*>(bias);
    float2* C2 = reinterpret_cast<float2*>(C);
    const float2* x2 = reinterpret_cast<const float2*>(x);
    const float2* u2 = reinterpret_cast<const float2*>(u);

#pragma unroll
    for (int mt = 0; mt < 2; ++mt) {
#pragma unroll
        for (int half = 0; half < 2; ++half) {
            int r = row0 + warp_m * 32 + mt * 16 + (lane >> 2) + half * 8;
            if (r >= n) continue;
#pragma unroll
            for (int nt = 0; nt < 2; ++nt) {
                int c = ch * 64 + warp_n * 16 + nt * 8 + (lane & 3) * 2;
                int ci = c >> 1;
                float2 bb = bias2[ci];
                float2 v;
                v.x = d[mt][nt][half * 2 + 0] + bb.x;
                v.y = d[mt][nt][half * 2 + 1] + bb.y;
                size_t gi = (size_t)r * 64 + ci;
                if constexpr (EP == 1) {
                    float2 o = C2[gi];
                    v.x += o.x; v.y += o.y;
                }
                if constexpr (EP == 2) {
                    float2 xv = x2[gi];
                    float2 uv = u2[ci];
                    v.x += uv.x * xv.x; v.y += uv.y * xv.y;
                }
                if constexpr (OUT_ACT) { v.x = ssp(v.x); v.y = ssp(v.y); }
                C2[gi] = v;
            }
        }
    }
}

// ---------------------------------------------------------------------------
// Edge kernel, MMA version + software pipelining:
//   - rbf for tile t+1 prefetched into registers before tile t's MMA
//   - epilogue gathers (j -> xjall) batched for MLP=8
// ---------------------------------------------------------------------------
#define ELDK 72
#define EW_PLANE (128 * ELDK * 2)   // 18432
#define EA_PLANE (64 * ELDK * 2)    // 9216
#define EG_LD 132
#define ESM_WHI 0
#define ESM_WLO (ESM_WHI + EW_PLANE)
#define ESM_AHI (ESM_WLO + EW_PLANE)
#define ESM_ALO (ESM_AHI + EA_PLANE)
#define ESM_G   (ESM_ALO + EA_PLANE)
#define ESM_TOTAL (ESM_G + 64 * EG_LD * 4)   // 89088 B

__global__ __launch_bounds__(256, 2)
void edge_mma(const float* __restrict__ rbf,
              const __nv_bfloat16* __restrict__ wkhi,
              const __nv_bfloat16* __restrict__ wklo,
              const float* __restrict__ xjall, const int* __restrict__ ii,
              const int* __restrict__ jj, float* __restrict__ mout) {
    extern __shared__ __align__(16) char sm[];
    uint32_t smb = smem_u32(sm);
    int tid = threadIdx.x;
    int wid = tid >> 5;
    int lane = tid & 31;

    // stage W planes: [128 c][64 k] bf16
    {
        const uint4* srcH = reinterpret_cast<const uint4*>(wkhi);
        const uint4* srcL = reinterpret_cast<const uint4*>(wklo);
#pragma unroll
        for (int it = 0; it < 4; ++it) {
            int idx = tid + it * 256;
            int row = idx >> 3;
            int seg = idx & 7;
            uint32_t off = (uint32_t)(row * ELDK + seg * 8) * 2;
            *reinterpret_cast<uint4*>(sm + ESM_WHI + off) = srcH[idx];
            *reinterpret_cast<uint4*>(sm + ESM_WLO + off) = srcL[idx];
        }
    }

    int warp_m = wid & 1;
    int warp_n = wid >> 1;
    int a_row = warp_m * 32 + (lane & 15);
    int a_k8 = (lane >> 4) * 8;
    int b_n = warp_n * 32 + (lane >> 4) * 8 + (lane & 7);
    int b_k8 = ((lane >> 3) & 1) * 8;

    int tx = tid & 31;
    int eg = tid >> 5;
    int c0 = tx * 4;
    long base = (long)blockIdx.x * 512;

    const float4* rbf4 = reinterpret_cast<const float4*>(rbf);

    int cur_i = -1;
    float racc[4] = {0.f, 0.f, 0.f, 0.f};

    // prefetch tile 0 rbf (4 float4 per thread)
    float4 pre[4];
#pragma unroll
    for (int s = 0; s < 4; ++s) {
        int idx = tid + s * 256;
        long e = base + (idx >> 4);
        pre[s] = (e < E_) ? rbf4[e * 16 + (idx & 15)]
                          : make_float4(0.f, 0.f, 0.f, 0.f);
    }

    for (int t = 0; t < 8; ++t) {
        __syncthreads();   // A/G free (all warps past previous epilogue)
        // convert prefetched rbf -> bf16 hi/lo smem
#pragma unroll
        for (int s = 0; s < 4; ++s) {
            int idx = tid + s * 256;
            int er = idx >> 4;
            int k4 = idx & 15;
            u64 hv, lv;
            split4(pre[s], hv, lv);
            uint32_t off = (uint32_t)(er * ELDK + k4 * 4) * 2;
            *reinterpret_cast<u64*>(sm + ESM_AHI + off) = hv;
            *reinterpret_cast<u64*>(sm + ESM_ALO + off) = lv;
        }
        __syncthreads();

        // prefetch next tile's rbf (latency hidden under MMA)
        if (t < 7) {
#pragma unroll
            for (int s = 0; s < 4; ++s) {
                int idx = tid + s * 256;
                long e = base + (t + 1) * 64 + (idx >> 4);
                pre[s] = (e < E_) ? rbf4[e * 16 + (idx & 15)]
                                  : make_float4(0.f, 0.f, 0.f, 0.f);
            }
        }

        // MMA: g[64 e][128 c] = rbf @ Wk2f^T, 3-term split, K=64
        float d[2][4][4];
#pragma unroll
        for (int mt = 0; mt < 2; ++mt)
#pragma unroll
            for (int nt = 0; nt < 4; ++nt)
#pragma unroll
                for (int q = 0; q < 4; ++q) d[mt][nt][q] = 0.f;

#pragma unroll
        for (int ks = 0; ks < 4; ++ks) {
            int kb = ks * 16;
            unsigned bh[2][4], bl[2][4], ah[2][4], al[2][4];
#pragma unroll
            for (int p = 0; p < 2; ++p) {
                uint32_t boff =
                    (uint32_t)((b_n + p * 16) * ELDK + kb + b_k8) * 2;
                ldsm4(bh[p], smb + ESM_WHI + boff);
                ldsm4(bl[p], smb + ESM_WLO + boff);
            }
#pragma unroll
            for (int mt = 0; mt < 2; ++mt) {
                uint32_t aoff =
                    (uint32_t)((a_row + mt * 16) * ELDK + kb + a_k8) * 2;
                ldsm4(ah[mt], smb + ESM_AHI + aoff);
                ldsm4(al[mt], smb + ESM_ALO + aoff);
            }
#pragma unroll
            for (int term = 0; term < 3; ++term) {
#pragma unroll
                for (int mt = 0; mt < 2; ++mt) {
#pragma unroll
                    for (int nt = 0; nt < 4; ++nt) {
                        const unsigned* af = (term == 2) ? al[mt] : ah[mt];
                        const unsigned* bf =
                            (term == 1) ? bl[nt >> 1] : bh[nt >> 1];
                        mma16816(d[mt][nt], af, bf[(nt & 1) * 2],
                                 bf[(nt & 1) * 2 + 1]);
                    }
                }
            }
        }

        // dump g to smem (fp32, padded rows)
#pragma unroll
        for (int mt = 0; mt < 2; ++mt)
#pragma unroll
            for (int half = 0; half < 2; ++half) {
                int row = warp_m * 32 + mt * 16 + (lane >> 2) + half * 8;
#pragma unroll
                for (int nt = 0; nt < 4; ++nt) {
                    int col = warp_n * 32 + nt * 8 + (lane & 3) * 2;
                    float2 v;
                    v.x = d[mt][nt][half * 2 + 0];
                    v.y = d[mt][nt][half * 2 + 1];
                    *reinterpret_cast<float2*>(
                        sm + ESM_G + (uint32_t)(row * EG_LD + col) * 4) = v;
                }
            }
        __syncthreads();

        // epilogue: batched gathers (MLP=8), then run-length scatter
        int iarr[8];
        float4 xv[8];
#pragma unroll
        for (int s = 0; s < 8; ++s) {
            long e = base + t * 64 + eg * 8 + s;
            if (e < E_) {
                iarr[s] = __ldg(ii + e);
                int j = __ldg(jj + e);
                xv[s] = __ldg(reinterpret_cast<const float4*>(
                                  xjall + (size_t)j * 128) + tx);
            } else {
                iarr[s] = -1;
                xv[s] = make_float4(0.f, 0.f, 0.f, 0.f);
            }
        }
#pragma unroll
        for (int s = 0; s < 8; ++s) {
            if (iarr[s] < 0) continue;
            float4 g4 = *reinterpret_cast<const float4*>(
                sm + ESM_G + (uint32_t)((eg * 8 + s) * EG_LD + c0) * 4);
            float v0 = g4.x * xv[s].x;
            float v1 = g4.y * xv[s].y;
            float v2 = g4.z * xv[s].z;
            float v3 = g4.w * xv[s].w;
            if (iarr[s] != cur_i) {
                if (cur_i >= 0) {
                    float* dst = mout + (size_t)cur_i * 128 + c0;
                    atomicAdd(dst + 0, racc[0]);
                    atomicAdd(dst + 1, racc[1]);
                    atomicAdd(dst + 2, racc[2]);
                    atomicAdd(dst + 3, racc[3]);
                }
                cur_i = iarr[s];
                racc[0] = v0; racc[1] = v1; racc[2] = v2; racc[3] = v3;
            } else {
                racc[0] += v0; racc[1] += v1; racc[2] += v2; racc[3] += v3;
            }
        }
    }
    if (cur_i >= 0) {
        float* dst = mout + (size_t)cur_i * 128 + c0;
        atomicAdd(dst + 0, racc[0]);
        atomicAdd(dst + 1, racc[1]);
        atomicAdd(dst + 2, racc[2]);
        atomicAdd(dst + 3, racc[3]);
    }
}

// ---------------------------------------------------------------------------
// Launch
// ---------------------------------------------------------------------------
extern "C" void kernel_launch(void* const* d_in, const int* in_sizes, int n_in,
                              void* d_out, int out_size) {
    const float* x    = (const float*)d_in[0];
    const float* rbf  = (const float*)d_in[1];
    const float* Wk2f = (const float*)d_in[2];
    const float* Wi   = (const float*)d_in[3];
    const float* bi   = (const float*)d_in[4];
    const float* Wj   = (const float*)d_in[5];
    const float* bj   = (const float*)d_in[6];
    const float* Wr1  = (const float*)d_in[7];
    const float* br1  = (const float*)d_in[8];
    const float* Wr2  = (const float*)d_in[9];
    const float* br2  = (const float*)d_in[10];
    const float* Wf   = (const float*)d_in[11];
    const float* bfb  = (const float*)d_in[12];
    const float* u    = (const float*)d_in[13];
    const int* idx_i  = (const int*)d_in[14];
    const int* idx_j  = (const int*)d_in[15];
    float* out = (float*)d_out;

    void *p_m, *p_xjall, *p_y, *p_hi, *p_lo, *p_wkh, *p_wkl;
    cudaGetSymbolAddress(&p_m, g_m);
    cudaGetSymbolAddress(&p_xjall, g_xjall);
    cudaGetSymbolAddress(&p_y, g_y);
    cudaGetSymbolAddress(&p_hi, g_wthi);
    cudaGetSymbolAddress(&p_lo, g_wtlo);
    cudaGetSymbolAddress(&p_wkh, g_wkhi);
    cudaGetSymbolAddress(&p_wkl, g_wklo);
    float* m = (float*)p_m;
    float* xjall = (float*)p_xjall;
    float* y = (float*)p_y;
    __nv_bfloat16* whi = (__nv_bfloat16*)p_hi;
    __nv_bfloat16* wlo = (__nv_bfloat16*)p_lo;
    __nv_bfloat16* wkhi = (__nv_bfloat16*)p_wkh;
    __nv_bfloat16* wklo = (__nv_bfloat16*)p_wkl;

    cudaFuncSetAttribute(gemm_mma<true, true, 0>,
                         cudaFuncAttributeMaxDynamicSharedMemorySize, SM_TOTAL);
    cudaFuncSetAttribute(gemm_mma<false, false, 1>,
                         cudaFuncAttributeMaxDynamicSharedMemorySize, SM_TOTAL);
    cudaFuncSetAttribute(gemm_mma<true, false, 2>,
                         cudaFuncAttributeMaxDynamicSharedMemorySize, SM_TOTAL);
    cudaFuncSetAttribute(edge_mma,
                         cudaFuncAttributeMaxDynamicSharedMemorySize, ESM_TOTAL);

    // one-time weight packing
    dim3 pw(64, 9);
    packw_kernel<<<pw, 256>>>(Wi, Wj, Wr1, Wr2, Wf, whi, wlo);
    packwk_kernel<<<32, 256>>>(Wk2f, wkhi, wklo);

    int gemm_blocks = ((N_ + 63) / 64) * 2;   // 1564 (row tile x col half)
    int edge_blocks = (E_ + 511) / 512;       // 1563

    // m = xi = ssp(ssp(x) @ Wi + bi)
    gemm_mma<true, true, 0><<<gemm_blocks, 256, SM_TOTAL>>>(
        x, whi + 0 * 16384, wlo + 0 * 16384, bi, m, nullptr, nullptr, N_);
    // xjall = ssp(ssp(x) @ Wj + bj)
    gemm_mma<true, true, 0><<<gemm_blocks, 256, SM_TOTAL>>>(
        x, whi + 1 * 16384, wlo + 1 * 16384, bj, xjall, nullptr, nullptr, N_);
    // m += segment_sum((rbf@Wk2f) * xjall[idx_j], idx_i)
    edge_mma<<<edge_blocks, 256, ESM_TOTAL>>>(rbf, wkhi, wklo, xjall,
                                              idx_i, idx_j, m);

    // residual blocks
    for (int l = 0; l < L_; ++l) {
        gemm_mma<true, true, 0><<<gemm_blocks, 256, SM_TOTAL>>>(
            m, whi + (2 + l) * 16384, wlo + (2 + l) * 16384,
            br1 + (size_t)l * F_, y, nullptr, nullptr, N_);
        gemm_mma<false, false, 1><<<gemm_blocks, 256, SM_TOTAL>>>(
            y, whi + (5 + l) * 16384, wlo + (5 + l) * 16384,
            br2 + (size_t)l * F_, m, nullptr, nullptr, N_);
    }

    // out = u * x + ssp(m) @ Wf + bf
    gemm_mma<true, false, 2><<<gemm_blocks, 256, SM_TOTAL>>>(
        m, whi + 8 * 16384, wlo + 8 * 16384, bfb, out, x, u, N_);
}